// round 8
// baseline (speedup 1.0000x reference)
#include <cuda_runtime.h>
#include <cuda_bf16.h>
#include <cstdint>

// Problem constants
#define B_ 4
#define S_ 2048
#define E_ 1024
#define H_ 16
#define D_ 64

// Scratch (device globals; no allocation allowed)
__device__ float g_Q[(size_t)B_ * H_ * S_ * D_];
__device__ float g_K[(size_t)B_ * H_ * S_ * D_];
__device__ float g_V[(size_t)B_ * H_ * S_ * D_];
__device__ float g_AO[(size_t)B_ * S_ * E_];

// Swizzled smem offset for GEMM tiles ([128][16] fp32 buffer)
__device__ __forceinline__ int SWZ(int r, int c) {
    return r * 16 + ((((c) >> 2) ^ ((r >> 1) & 3)) << 2) + (c & 3);
}

__device__ __forceinline__ float to_tf32(float x) {
    uint32_t u;
    asm("cvt.rna.tf32.f32 %0, %1;" : "=r"(u) : "f"(x));
    return __uint_as_float(u);
}

__device__ __forceinline__ float4 cvt4(float4 v) {
    return make_float4(to_tf32(v.x), to_tf32(v.y), to_tf32(v.z), to_tf32(v.w));
}

__device__ __forceinline__ void mma_tf32(float* c, const uint32_t* a, const uint32_t* b) {
    asm volatile(
        "mma.sync.aligned.m16n8k8.row.col.f32.tf32.tf32.f32 "
        "{%0,%1,%2,%3}, {%4,%5,%6,%7}, {%8,%9}, {%0,%1,%2,%3};"
        : "+f"(c[0]), "+f"(c[1]), "+f"(c[2]), "+f"(c[3])
        : "r"(a[0]), "r"(a[1]), "r"(a[2]), "r"(a[3]), "r"(b[0]), "r"(b[1]));
}

// ---------------------------------------------------------------------------
// TF32 tensor-core GEMM: C[M,N] = A[M,K] * W[N,K]^T
// Tile 128x128x16, 256 threads, warp grid 2x4, warp tile 64x32.
// DOUBLE-BUFFERED smem, ONE __syncthreads per K-chunk; next chunk's LDG is
// issued before the MMA phase so global latency overlaps compute.
// blockIdx.z selects (W, C). SPLIT=true writes [B,H,S,D].
// ---------------------------------------------------------------------------
template <bool SPLIT>
__global__ __launch_bounds__(256, 2) void gemm_tf32(
    const float* __restrict__ A,
    const float* __restrict__ W0, const float* __restrict__ W1,
    const float* __restrict__ W2,
    float* __restrict__ C0, float* __restrict__ C1, float* __restrict__ C2) {
    const int K = E_;
    __shared__ float As[2][128 * 16];
    __shared__ float Bs[2][128 * 16];

    const float* W = W0;
    float* C = C0;
    if (blockIdx.z == 1) { W = W1; C = C1; }
    else if (blockIdx.z == 2) { W = W2; C = C2; }

    int tid = threadIdx.x;
    int bm = blockIdx.y * 128, bn = blockIdx.x * 128;
    int wid = tid >> 5, lane = tid & 31;
    int lr = lane >> 2, lc = lane & 3;
    int mb = (wid & 1) * 64;
    int nb = (wid >> 1) * 32;

    int ldr = tid >> 2;          // 0..63
    int ldc = (tid & 3) << 2;    // 0,4,8,12

    const float* Ap = A + (size_t)(bm + ldr) * K + ldc;
    const float* Wp = W + (size_t)(bn + ldr) * K + ldc;

    float acc[4][4][4];
#pragma unroll
    for (int mt = 0; mt < 4; mt++)
#pragma unroll
        for (int nt = 0; nt < 4; nt++)
#pragma unroll
            for (int i = 0; i < 4; i++) acc[mt][nt][i] = 0.f;

    const int s0 = (ldr >> 1) & 3;
    const int s1 = ((ldr + 64) >> 1) & 3;
    const int o0 = ldr * 16 + (((ldc >> 2) ^ s0) << 2);
    const int o1 = (ldr + 64) * 16 + (((ldc >> 2) ^ s1) << 2);

    // Prologue: load + store chunk 0 into buffer 0
    {
        float4 av0 = *(const float4*)(Ap);
        float4 av1 = *(const float4*)(Ap + (size_t)64 * K);
        float4 wv0 = *(const float4*)(Wp);
        float4 wv1 = *(const float4*)(Wp + (size_t)64 * K);
        *(float4*)&As[0][o0] = cvt4(av0);
        *(float4*)&As[0][o1] = cvt4(av1);
        *(float4*)&Bs[0][o0] = cvt4(wv0);
        *(float4*)&Bs[0][o1] = cvt4(wv1);
    }
    __syncthreads();

    const int NCHUNK = K / 16;  // 64
#pragma unroll 1
    for (int c = 0; c < NCHUNK; c++) {
        const int s = c & 1;
        const float* Asb = &As[s][0];
        const float* Bsb = &Bs[s][0];

        // Issue next chunk's loads NOW; latency overlaps the MMA phase below.
        float4 av0, av1, wv0, wv1;
        const bool more = (c + 1 < NCHUNK);
        if (more) {
            int kc = (c + 1) * 16;
            av0 = *(const float4*)(Ap + kc);
            av1 = *(const float4*)(Ap + (size_t)64 * K + kc);
            wv0 = *(const float4*)(Wp + kc);
            wv1 = *(const float4*)(Wp + (size_t)64 * K + kc);
        }

        // MMA phase on buffer s
#pragma unroll
        for (int k0 = 0; k0 < 16; k0 += 8) {
            uint32_t af[4][4], bf[4][2];
#pragma unroll
            for (int mt = 0; mt < 4; mt++) {
                int m = mb + mt * 16 + lr;
                af[mt][0] = __float_as_uint(Asb[SWZ(m, k0 + lc)]);
                af[mt][1] = __float_as_uint(Asb[SWZ(m + 8, k0 + lc)]);
                af[mt][2] = __float_as_uint(Asb[SWZ(m, k0 + 4 + lc)]);
                af[mt][3] = __float_as_uint(Asb[SWZ(m + 8, k0 + 4 + lc)]);
            }
#pragma unroll
            for (int nt = 0; nt < 4; nt++) {
                int n = nb + nt * 8 + lr;
                bf[nt][0] = __float_as_uint(Bsb[SWZ(n, k0 + lc)]);
                bf[nt][1] = __float_as_uint(Bsb[SWZ(n, k0 + 4 + lc)]);
            }
#pragma unroll
            for (int mt = 0; mt < 4; mt++)
#pragma unroll
                for (int nt = 0; nt < 4; nt++)
                    mma_tf32(acc[mt][nt], af[mt], bf[nt]);
        }

        // Store next chunk into the other buffer (no conflict with readers of s)
        if (more) {
            float* Anb = &As[s ^ 1][0];
            float* Bnb = &Bs[s ^ 1][0];
            *(float4*)&Anb[o0] = cvt4(av0);
            *(float4*)&Anb[o1] = cvt4(av1);
            *(float4*)&Bnb[o0] = cvt4(wv0);
            *(float4*)&Bnb[o1] = cvt4(wv1);
        }
        __syncthreads();
    }

    // Epilogue
#pragma unroll
    for (int mt = 0; mt < 4; mt++) {
#pragma unroll
        for (int nt = 0; nt < 4; nt++) {
            int row = bm + mb + mt * 16 + lr;
            int col = bn + nb + nt * 8 + lc * 2;
#pragma unroll
            for (int half = 0; half < 2; half++) {
                int m = row + half * 8;
                float2 v = make_float2(acc[mt][nt][half * 2],
                                       acc[mt][nt][half * 2 + 1]);
                if (!SPLIT) {
                    *(float2*)(C + (size_t)m * E_ + col) = v;
                } else {
                    int b = m >> 11, sq = m & 2047;
                    int h = col >> 6, d = col & 63;
                    *(float2*)(C + ((((size_t)b * H_ + h) * S_ + sq) * D_ + d)) = v;
                }
            }
        }
    }
}

// ---------------------------------------------------------------------------
// Tensor-core flash attention (tf32 mma, fp32 softmax). Unchanged from R3.
// ---------------------------------------------------------------------------
__global__ __launch_bounds__(256) void flash_tc(const float* __restrict__ Q,
                                                const float* __restrict__ K,
                                                const float* __restrict__ V,
                                                const int* __restrict__ amask,
                                                float* __restrict__ out) {
    extern __shared__ float smf[];
    float* Qs = smf;                   // 128 x 68
    float* Ks = Qs + 128 * 68;         // 64 x 68
    float* Vs = Ks + 64 * 68;          // 64 x 72
    __shared__ unsigned mkb[2];

    const int tid = threadIdx.x;
    const int qt = blockIdx.x;
    const int bh = blockIdx.y;
    const int b = bh >> 4, h = bh & 15;
    const int qbase = qt * 128;

    const int lane = tid & 31, wid = tid >> 5;
    const int lr = lane >> 2, lc = lane & 3;
    const int wb = wid * 16;

    {
        const float* Qb = Q + ((size_t)bh * S_ + qbase) * D_;
        for (int e = tid; e < 2048; e += 256) {
            int r = e >> 4, c4 = e & 15;
            float4 v = ((const float4*)Qb)[e];
            v.x *= 0.125f; v.y *= 0.125f; v.z *= 0.125f; v.w *= 0.125f;
            *(float4*)&Qs[r * 68 + c4 * 4] = cvt4(v);
        }
    }

    const int grow0 = qbase + wb + lr;
    const int grow1 = grow0 + 8;

    float oacc[8][4];
#pragma unroll
    for (int nt = 0; nt < 8; nt++)
#pragma unroll
        for (int j = 0; j < 4; j++) oacc[nt][j] = 0.f;

    float mlo = -1e30f, mhi = -1e30f, llo = 0.f, lhi = 0.f;

    const int ntiles = 2 * qt + 2;
    for (int kt = 0; kt < ntiles; kt++) {
        __syncthreads();

        const float* Kb = K + ((size_t)bh * S_ + kt * 64) * D_;
        const float* Vb = V + ((size_t)bh * S_ + kt * 64) * D_;
        for (int e = tid; e < 1024; e += 256) {
            int r = e >> 4, c4 = e & 15;
            float4 kv = ((const float4*)Kb)[e];
            *(float4*)&Ks[r * 68 + c4 * 4] = cvt4(kv);
            float4 vv = ((const float4*)Vb)[e];
            *(float4*)&Vs[r * 72 + c4 * 4] = cvt4(vv);
        }
        if (tid < 64) {
            int m = amask[b * S_ + kt * 64 + tid];
            unsigned bal = __ballot_sync(0xffffffffu, m != 0);
            if ((tid & 31) == 0) mkb[tid >> 5] = bal;
        }
        __syncthreads();

        float sacc[8][4];
#pragma unroll
        for (int nt = 0; nt < 8; nt++)
#pragma unroll
            for (int j = 0; j < 4; j++) sacc[nt][j] = 0.f;

#pragma unroll
        for (int ks = 0; ks < 8; ks++) {
            int k0 = ks * 8;
            uint32_t a[4];
            a[0] = __float_as_uint(Qs[(wb + lr) * 68 + k0 + lc]);
            a[1] = __float_as_uint(Qs[(wb + lr + 8) * 68 + k0 + lc]);
            a[2] = __float_as_uint(Qs[(wb + lr) * 68 + k0 + 4 + lc]);
            a[3] = __float_as_uint(Qs[(wb + lr + 8) * 68 + k0 + 4 + lc]);
#pragma unroll
            for (int nt = 0; nt < 8; nt++) {
                uint32_t bb[2];
                bb[0] = __float_as_uint(Ks[(nt * 8 + lr) * 68 + k0 + lc]);
                bb[1] = __float_as_uint(Ks[(nt * 8 + lr) * 68 + k0 + 4 + lc]);
                mma_tf32(sacc[nt], a, bb);
            }
        }

        unsigned mb0 = mkb[0], mb1 = mkb[1];
        bool diag = (kt >= 2 * qt);
        bool pad = (mb0 & mb1) != 0xffffffffu;
        if (diag || pad) {
#pragma unroll
            for (int nt = 0; nt < 8; nt++) {
#pragma unroll
                for (int j = 0; j < 4; j++) {
                    int colL = nt * 8 + 2 * lc + (j & 1);
                    int gcol = kt * 64 + colL;
                    int grow = (j < 2) ? grow0 : grow1;
                    unsigned bit = ((colL < 32 ? mb0 : mb1) >> (colL & 31)) & 1u;
                    if (!bit || gcol > grow) sacc[nt][j] = -1e30f;
                }
            }
        }

        float tlo = -1e30f, thi = -1e30f;
#pragma unroll
        for (int nt = 0; nt < 8; nt++) {
            tlo = fmaxf(tlo, fmaxf(sacc[nt][0], sacc[nt][1]));
            thi = fmaxf(thi, fmaxf(sacc[nt][2], sacc[nt][3]));
        }
        tlo = fmaxf(tlo, __shfl_xor_sync(0xffffffffu, tlo, 1));
        tlo = fmaxf(tlo, __shfl_xor_sync(0xffffffffu, tlo, 2));
        thi = fmaxf(thi, __shfl_xor_sync(0xffffffffu, thi, 1));
        thi = fmaxf(thi, __shfl_xor_sync(0xffffffffu, thi, 2));

        float nmlo = fmaxf(mlo, tlo), nmhi = fmaxf(mhi, thi);
        float alo = __expf(mlo - nmlo), ahi = __expf(mhi - nmhi);
        mlo = nmlo; mhi = nmhi;

        float slo = 0.f, shi = 0.f;
#pragma unroll
        for (int nt = 0; nt < 8; nt++) {
            float p0 = to_tf32(__expf(sacc[nt][0] - nmlo));
            float p1 = to_tf32(__expf(sacc[nt][1] - nmlo));
            float p2 = to_tf32(__expf(sacc[nt][2] - nmhi));
            float p3 = to_tf32(__expf(sacc[nt][3] - nmhi));
            sacc[nt][0] = p0; sacc[nt][1] = p1;
            sacc[nt][2] = p2; sacc[nt][3] = p3;
            slo += p0 + p1; shi += p2 + p3;
        }
        slo += __shfl_xor_sync(0xffffffffu, slo, 1);
        slo += __shfl_xor_sync(0xffffffffu, slo, 2);
        shi += __shfl_xor_sync(0xffffffffu, shi, 1);
        shi += __shfl_xor_sync(0xffffffffu, shi, 2);
        llo = llo * alo + slo;
        lhi = lhi * ahi + shi;

#pragma unroll
        for (int nt = 0; nt < 8; nt++) {
            oacc[nt][0] *= alo; oacc[nt][1] *= alo;
            oacc[nt][2] *= ahi; oacc[nt][3] *= ahi;
        }

        const int src0 = (lane & 28) | (lc >> 1);
        const int src1 = src0 + 2;
#pragma unroll
        for (int ks = 0; ks < 8; ks++) {
            float p0 = sacc[ks][0], p1 = sacc[ks][1];
            float p2 = sacc[ks][2], p3 = sacc[ks][3];
            float u0 = __shfl_sync(0xffffffffu, p0, src0);
            float u1 = __shfl_sync(0xffffffffu, p1, src0);
            float u2 = __shfl_sync(0xffffffffu, p2, src0);
            float u3 = __shfl_sync(0xffffffffu, p3, src0);
            float v0 = __shfl_sync(0xffffffffu, p0, src1);
            float v1 = __shfl_sync(0xffffffffu, p1, src1);
            float v2 = __shfl_sync(0xffffffffu, p2, src1);
            float v3 = __shfl_sync(0xffffffffu, p3, src1);
            uint32_t a[4];
            a[0] = __float_as_uint((lc & 1) ? u1 : u0);
            a[1] = __float_as_uint((lc & 1) ? u3 : u2);
            a[2] = __float_as_uint((lc & 1) ? v1 : v0);
            a[3] = __float_as_uint((lc & 1) ? v3 : v2);
#pragma unroll
            for (int nt = 0; nt < 8; nt++) {
                uint32_t bb[2];
                bb[0] = __float_as_uint(Vs[(ks * 8 + lc) * 72 + nt * 8 + lr]);
                bb[1] = __float_as_uint(Vs[(ks * 8 + 4 + lc) * 72 + nt * 8 + lr]);
                mma_tf32(oacc[nt], a, bb);
            }
        }
    }

    float il0 = 1.f / llo, il1 = 1.f / lhi;
#pragma unroll
    for (int nt = 0; nt < 8; nt++) {
        int col = nt * 8 + 2 * lc;
        float* p0 = out + ((size_t)b * S_ + grow0) * E_ + h * D_ + col;
        float* p1 = out + ((size_t)b * S_ + grow1) * E_ + h * D_ + col;
        *(float2*)p0 = make_float2(oacc[nt][0] * il0, oacc[nt][1] * il0);
        *(float2*)p1 = make_float2(oacc[nt][2] * il1, oacc[nt][3] * il1);
    }
}

// ---------------------------------------------------------------------------
// Launch
// ---------------------------------------------------------------------------
extern "C" void kernel_launch(void* const* d_in, const int* in_sizes, int n_in,
                              void* d_out, int out_size) {
    const float* x     = (const float*)d_in[0];
    const int*   amask = (const int*)d_in[1];
    const float* wq    = (const float*)d_in[2];
    const float* wk    = (const float*)d_in[3];
    const float* wv    = (const float*)d_in[4];
    const float* wo    = (const float*)d_in[5];
    float* out = (float*)d_out;

    float *qp, *kp, *vp, *aop;
    cudaGetSymbolAddress((void**)&qp, g_Q);
    cudaGetSymbolAddress((void**)&kp, g_K);
    cudaGetSymbolAddress((void**)&vp, g_V);
    cudaGetSymbolAddress((void**)&aop, g_AO);

    // Fused Q/K/V projections
    gemm_tf32<true><<<dim3(E_ / 128, (B_ * S_) / 128, 3), 256>>>(
        x, wq, wk, wv, qp, kp, vp);

    // Tensor-core flash attention
    size_t fa_smem = (128 * 68 + 64 * 68 + 64 * 72) * sizeof(float);
    cudaFuncSetAttribute(flash_tc, cudaFuncAttributeMaxDynamicSharedMemorySize,
                         (int)fa_smem);
    flash_tc<<<dim3(S_ / 128, B_ * H_), 256, fa_smem>>>(qp, kp, vp, amask, aop);

    // Output projection
    gemm_tf32<false><<<dim3(E_ / 128, (B_ * S_) / 128, 1), 256>>>(
        aop, wo, wo, wo, out, out, out);
}

// round 9
// speedup vs baseline: 1.1134x; 1.1134x over previous
#include <cuda_runtime.h>
#include <cuda_bf16.h>
#include <cstdint>

// Problem constants
#define B_ 4
#define S_ 2048
#define E_ 1024
#define H_ 16
#define D_ 64

// Scratch (device globals; no allocation allowed)
__device__ float g_Q[(size_t)B_ * H_ * S_ * D_];
__device__ float g_K[(size_t)B_ * H_ * S_ * D_];
__device__ float g_V[(size_t)B_ * H_ * S_ * D_];
__device__ float g_AO[(size_t)B_ * S_ * E_];
__device__ float g_X[(size_t)B_ * S_ * E_];    // tf32-rounded x
__device__ float g_WQ[(size_t)E_ * E_];        // tf32-rounded weights
__device__ float g_WK[(size_t)E_ * E_];
__device__ float g_WV[(size_t)E_ * E_];
__device__ float g_WO[(size_t)E_ * E_];

// Swizzled smem offset for GEMM tiles ([128][16] fp32 buffer)
__device__ __forceinline__ int SWZ(int r, int c) {
    return r * 16 + ((((c) >> 2) ^ ((r >> 1) & 3)) << 2) + (c & 3);
}

__device__ __forceinline__ float to_tf32(float x) {
    uint32_t u;
    asm("cvt.rna.tf32.f32 %0, %1;" : "=r"(u) : "f"(x));
    return __uint_as_float(u);
}

__device__ __forceinline__ float4 cvt4(float4 v) {
    return make_float4(to_tf32(v.x), to_tf32(v.y), to_tf32(v.z), to_tf32(v.w));
}

__device__ __forceinline__ void mma_tf32(float* c, const uint32_t* a, const uint32_t* b) {
    asm volatile(
        "mma.sync.aligned.m16n8k8.row.col.f32.tf32.tf32.f32 "
        "{%0,%1,%2,%3}, {%4,%5,%6,%7}, {%8,%9}, {%0,%1,%2,%3};"
        : "+f"(c[0]), "+f"(c[1]), "+f"(c[2]), "+f"(c[3])
        : "r"(a[0]), "r"(a[1]), "r"(a[2]), "r"(a[3]), "r"(b[0]), "r"(b[1]));
}

__device__ __forceinline__ void cp16(uint32_t dst, const void* src) {
    asm volatile("cp.async.cg.shared.global [%0], [%1], 16;"
                 :: "r"(dst), "l"(src) : "memory");
}
#define CP_COMMIT() asm volatile("cp.async.commit_group;" ::: "memory")
#define CP_WAIT1()  asm volatile("cp.async.wait_group 1;" ::: "memory")

// ---------------------------------------------------------------------------
// Input conversion: round x and the 4 weight matrices to tf32 once.
// float4-grid: 2M (x) + 4 x 256K (weights) = 3,145,728 float4 elements.
// ---------------------------------------------------------------------------
__global__ __launch_bounds__(256) void cvt_inputs(
    const float* __restrict__ x,
    const float* __restrict__ wq, const float* __restrict__ wk,
    const float* __restrict__ wv, const float* __restrict__ wo,
    float* __restrict__ xt,
    float* __restrict__ wqt, float* __restrict__ wkt,
    float* __restrict__ wvt, float* __restrict__ wot) {
    const int NX = (B_ * S_ * E_) / 4;   // 2,097,152
    const int NW = (E_ * E_) / 4;        // 262,144
    int i = blockIdx.x * 256 + threadIdx.x;
    if (i < NX) {
        ((float4*)xt)[i] = cvt4(((const float4*)x)[i]);
        return;
    }
    i -= NX;
    const float* s;
    float* d;
    if (i < NW)          { s = wq; d = wqt; }
    else if (i < 2 * NW) { s = wk; d = wkt; i -= NW; }
    else if (i < 3 * NW) { s = wv; d = wvt; i -= 2 * NW; }
    else                 { s = wo; d = wot; i -= 3 * NW; }
    ((float4*)d)[i] = cvt4(((const float4*)s)[i]);
}

// ---------------------------------------------------------------------------
// TF32 tensor-core GEMM: C[M,N] = A[M,K] * W[N,K]^T
// Inputs are ALREADY tf32-rounded. cp.async 3-stage pipeline, one sync/chunk.
// Tile 128x128x16, 256 threads, warp grid 2x4, warp tile 64x32.
// blockIdx.z selects (W, C). SPLIT=true writes [B,H,S,D] (tf32-rounded).
// ---------------------------------------------------------------------------
template <bool SPLIT>
__global__ __launch_bounds__(256, 2) void gemm_tf32(
    const float* __restrict__ A,
    const float* __restrict__ W0, const float* __restrict__ W1,
    const float* __restrict__ W2,
    float* __restrict__ C0, float* __restrict__ C1, float* __restrict__ C2) {
    const int K = E_;
    __shared__ float As[3][128 * 16];   // 24 KB
    __shared__ float Bs[3][128 * 16];   // 24 KB

    const float* W = W0;
    float* C = C0;
    if (blockIdx.z == 1) { W = W1; C = C1; }
    else if (blockIdx.z == 2) { W = W2; C = C2; }

    int tid = threadIdx.x;
    int bm = blockIdx.y * 128, bn = blockIdx.x * 128;
    int wid = tid >> 5, lane = tid & 31;
    int lr = lane >> 2, lc = lane & 3;
    int mb = (wid & 1) * 64;
    int nb = (wid >> 1) * 32;

    int ldr = tid >> 2;          // 0..63
    int ldc = (tid & 3) << 2;    // 0,4,8,12 (floats)

    const float* Ap = A + (size_t)(bm + ldr) * K + ldc;
    const float* Wp = W + (size_t)(bn + ldr) * K + ldc;

    // swizzled dst offsets (floats) for rows ldr and ldr+64
    const int s0 = (ldr >> 1) & 3;
    const int s1 = ((ldr + 64) >> 1) & 3;
    const int o0 = ldr * 16 + (((ldc >> 2) ^ s0) << 2);
    const int o1 = (ldr + 64) * 16 + (((ldc >> 2) ^ s1) << 2);

    const uint32_t sa = (uint32_t)__cvta_generic_to_shared(&As[0][0]);
    const uint32_t sb = (uint32_t)__cvta_generic_to_shared(&Bs[0][0]);
    const uint32_t a0b = sa + o0 * 4, a1b = sa + o1 * 4;
    const uint32_t b0b = sb + o0 * 4, b1b = sb + o1 * 4;

    float acc[4][4][4];
#pragma unroll
    for (int mt = 0; mt < 4; mt++)
#pragma unroll
        for (int nt = 0; nt < 4; nt++)
#pragma unroll
            for (int i = 0; i < 4; i++) acc[mt][nt][i] = 0.f;

    const int NCHUNK = K / 16;  // 64

    // Prologue: issue chunks 0 and 1 (one commit group each)
#pragma unroll
    for (int c = 0; c < 2; c++) {
        uint32_t st = (uint32_t)c * 8192u;  // stage stride bytes
        int kc = c * 16;
        cp16(a0b + st, Ap + kc);
        cp16(a1b + st, Ap + (size_t)64 * K + kc);
        cp16(b0b + st, Wp + kc);
        cp16(b1b + st, Wp + (size_t)64 * K + kc);
        CP_COMMIT();
    }

#pragma unroll 1
    for (int c = 0; c < NCHUNK; c++) {
        CP_WAIT1();
        __syncthreads();

        // Issue chunk c+2 into stage (c+2)%3 (== stage read at body c-1)
        if (c + 2 < NCHUNK) {
            uint32_t st = (uint32_t)((c + 2) % 3) * 8192u;
            int kc = (c + 2) * 16;
            cp16(a0b + st, Ap + kc);
            cp16(a1b + st, Ap + (size_t)64 * K + kc);
            cp16(b0b + st, Wp + kc);
            cp16(b1b + st, Wp + (size_t)64 * K + kc);
        }
        CP_COMMIT();

        // MMA on stage c%3
        const float* Asb = &As[c % 3][0];
        const float* Bsb = &Bs[c % 3][0];
#pragma unroll
        for (int k0 = 0; k0 < 16; k0 += 8) {
            uint32_t af[4][4], bf[4][2];
#pragma unroll
            for (int mt = 0; mt < 4; mt++) {
                int m = mb + mt * 16 + lr;
                af[mt][0] = __float_as_uint(Asb[SWZ(m, k0 + lc)]);
                af[mt][1] = __float_as_uint(Asb[SWZ(m + 8, k0 + lc)]);
                af[mt][2] = __float_as_uint(Asb[SWZ(m, k0 + 4 + lc)]);
                af[mt][3] = __float_as_uint(Asb[SWZ(m + 8, k0 + 4 + lc)]);
            }
#pragma unroll
            for (int nt = 0; nt < 4; nt++) {
                int n = nb + nt * 8 + lr;
                bf[nt][0] = __float_as_uint(Bsb[SWZ(n, k0 + lc)]);
                bf[nt][1] = __float_as_uint(Bsb[SWZ(n, k0 + 4 + lc)]);
            }
#pragma unroll
            for (int mt = 0; mt < 4; mt++)
#pragma unroll
                for (int nt = 0; nt < 4; nt++)
                    mma_tf32(acc[mt][nt], af[mt], bf[nt]);
        }
    }

    // Epilogue (SPLIT path pre-rounds to tf32 for the flash consumer)
#pragma unroll
    for (int mt = 0; mt < 4; mt++) {
#pragma unroll
        for (int nt = 0; nt < 4; nt++) {
            int row = bm + mb + mt * 16 + lr;
            int col = bn + nb + nt * 8 + lc * 2;
#pragma unroll
            for (int half = 0; half < 2; half++) {
                int m = row + half * 8;
                float v0 = acc[mt][nt][half * 2], v1 = acc[mt][nt][half * 2 + 1];
                if (!SPLIT) {
                    *(float2*)(C + (size_t)m * E_ + col) = make_float2(v0, v1);
                } else {
                    int b = m >> 11, sq = m & 2047;
                    int h = col >> 6, d = col & 63;
                    *(float2*)(C + ((((size_t)b * H_ + h) * S_ + sq) * D_ + d)) =
                        make_float2(to_tf32(v0), to_tf32(v1));
                }
            }
        }
    }
}

// ---------------------------------------------------------------------------
// Tensor-core flash attention (tf32 mma, fp32 softmax).
// Q/K/V are already tf32-rounded; loads skip cvt (0.125 Q-scale is exact).
// Writes AO tf32-rounded for the O-projection GEMM.
// ---------------------------------------------------------------------------
__global__ __launch_bounds__(256) void flash_tc(const float* __restrict__ Q,
                                                const float* __restrict__ K,
                                                const float* __restrict__ V,
                                                const int* __restrict__ amask,
                                                float* __restrict__ out) {
    extern __shared__ float smf[];
    float* Qs = smf;                   // 128 x 68
    float* Ks = Qs + 128 * 68;         // 64 x 68
    float* Vs = Ks + 64 * 68;          // 64 x 72
    __shared__ unsigned mkb[2];

    const int tid = threadIdx.x;
    const int qt = blockIdx.x;
    const int bh = blockIdx.y;
    const int b = bh >> 4, h = bh & 15;
    const int qbase = qt * 128;

    const int lane = tid & 31, wid = tid >> 5;
    const int lr = lane >> 2, lc = lane & 3;
    const int wb = wid * 16;

    {
        const float* Qb = Q + ((size_t)bh * S_ + qbase) * D_;
        for (int e = tid; e < 2048; e += 256) {
            int r = e >> 4, c4 = e & 15;
            float4 v = ((const float4*)Qb)[e];
            *(float4*)&Qs[r * 68 + c4 * 4] =
                make_float4(v.x * 0.125f, v.y * 0.125f, v.z * 0.125f, v.w * 0.125f);
        }
    }

    const int grow0 = qbase + wb + lr;
    const int grow1 = grow0 + 8;

    float oacc[8][4];
#pragma unroll
    for (int nt = 0; nt < 8; nt++)
#pragma unroll
        for (int j = 0; j < 4; j++) oacc[nt][j] = 0.f;

    float mlo = -1e30f, mhi = -1e30f, llo = 0.f, lhi = 0.f;

    const int ntiles = 2 * qt + 2;
    for (int kt = 0; kt < ntiles; kt++) {
        __syncthreads();

        const float* Kb = K + ((size_t)bh * S_ + kt * 64) * D_;
        const float* Vb = V + ((size_t)bh * S_ + kt * 64) * D_;
        for (int e = tid; e < 1024; e += 256) {
            int r = e >> 4, c4 = e & 15;
            *(float4*)&Ks[r * 68 + c4 * 4] = ((const float4*)Kb)[e];
            *(float4*)&Vs[r * 72 + c4 * 4] = ((const float4*)Vb)[e];
        }
        if (tid < 64) {
            int m = amask[b * S_ + kt * 64 + tid];
            unsigned bal = __ballot_sync(0xffffffffu, m != 0);
            if ((tid & 31) == 0) mkb[tid >> 5] = bal;
        }
        __syncthreads();

        float sacc[8][4];
#pragma unroll
        for (int nt = 0; nt < 8; nt++)
#pragma unroll
            for (int j = 0; j < 4; j++) sacc[nt][j] = 0.f;

#pragma unroll
        for (int ks = 0; ks < 8; ks++) {
            int k0 = ks * 8;
            uint32_t a[4];
            a[0] = __float_as_uint(Qs[(wb + lr) * 68 + k0 + lc]);
            a[1] = __float_as_uint(Qs[(wb + lr + 8) * 68 + k0 + lc]);
            a[2] = __float_as_uint(Qs[(wb + lr) * 68 + k0 + 4 + lc]);
            a[3] = __float_as_uint(Qs[(wb + lr + 8) * 68 + k0 + 4 + lc]);
#pragma unroll
            for (int nt = 0; nt < 8; nt++) {
                uint32_t bb[2];
                bb[0] = __float_as_uint(Ks[(nt * 8 + lr) * 68 + k0 + lc]);
                bb[1] = __float_as_uint(Ks[(nt * 8 + lr) * 68 + k0 + 4 + lc]);
                mma_tf32(sacc[nt], a, bb);
            }
        }

        unsigned mb0 = mkb[0], mb1 = mkb[1];
        bool diag = (kt >= 2 * qt);
        bool pad = (mb0 & mb1) != 0xffffffffu;
        if (diag || pad) {
#pragma unroll
            for (int nt = 0; nt < 8; nt++) {
#pragma unroll
                for (int j = 0; j < 4; j++) {
                    int colL = nt * 8 + 2 * lc + (j & 1);
                    int gcol = kt * 64 + colL;
                    int grow = (j < 2) ? grow0 : grow1;
                    unsigned bit = ((colL < 32 ? mb0 : mb1) >> (colL & 31)) & 1u;
                    if (!bit || gcol > grow) sacc[nt][j] = -1e30f;
                }
            }
        }

        float tlo = -1e30f, thi = -1e30f;
#pragma unroll
        for (int nt = 0; nt < 8; nt++) {
            tlo = fmaxf(tlo, fmaxf(sacc[nt][0], sacc[nt][1]));
            thi = fmaxf(thi, fmaxf(sacc[nt][2], sacc[nt][3]));
        }
        tlo = fmaxf(tlo, __shfl_xor_sync(0xffffffffu, tlo, 1));
        tlo = fmaxf(tlo, __shfl_xor_sync(0xffffffffu, tlo, 2));
        thi = fmaxf(thi, __shfl_xor_sync(0xffffffffu, thi, 1));
        thi = fmaxf(thi, __shfl_xor_sync(0xffffffffu, thi, 2));

        float nmlo = fmaxf(mlo, tlo), nmhi = fmaxf(mhi, thi);
        float alo = __expf(mlo - nmlo), ahi = __expf(mhi - nmhi);
        mlo = nmlo; mhi = nmhi;

        float slo = 0.f, shi = 0.f;
#pragma unroll
        for (int nt = 0; nt < 8; nt++) {
            float p0 = to_tf32(__expf(sacc[nt][0] - nmlo));
            float p1 = to_tf32(__expf(sacc[nt][1] - nmlo));
            float p2 = to_tf32(__expf(sacc[nt][2] - nmhi));
            float p3 = to_tf32(__expf(sacc[nt][3] - nmhi));
            sacc[nt][0] = p0; sacc[nt][1] = p1;
            sacc[nt][2] = p2; sacc[nt][3] = p3;
            slo += p0 + p1; shi += p2 + p3;
        }
        slo += __shfl_xor_sync(0xffffffffu, slo, 1);
        slo += __shfl_xor_sync(0xffffffffu, slo, 2);
        shi += __shfl_xor_sync(0xffffffffu, shi, 1);
        shi += __shfl_xor_sync(0xffffffffu, shi, 2);
        llo = llo * alo + slo;
        lhi = lhi * ahi + shi;

#pragma unroll
        for (int nt = 0; nt < 8; nt++) {
            oacc[nt][0] *= alo; oacc[nt][1] *= alo;
            oacc[nt][2] *= ahi; oacc[nt][3] *= ahi;
        }

        const int src0 = (lane & 28) | (lc >> 1);
        const int src1 = src0 + 2;
#pragma unroll
        for (int ks = 0; ks < 8; ks++) {
            float p0 = sacc[ks][0], p1 = sacc[ks][1];
            float p2 = sacc[ks][2], p3 = sacc[ks][3];
            float u0 = __shfl_sync(0xffffffffu, p0, src0);
            float u1 = __shfl_sync(0xffffffffu, p1, src0);
            float u2 = __shfl_sync(0xffffffffu, p2, src0);
            float u3 = __shfl_sync(0xffffffffu, p3, src0);
            float v0 = __shfl_sync(0xffffffffu, p0, src1);
            float v1 = __shfl_sync(0xffffffffu, p1, src1);
            float v2 = __shfl_sync(0xffffffffu, p2, src1);
            float v3 = __shfl_sync(0xffffffffu, p3, src1);
            uint32_t a[4];
            a[0] = __float_as_uint((lc & 1) ? u1 : u0);
            a[1] = __float_as_uint((lc & 1) ? u3 : u2);
            a[2] = __float_as_uint((lc & 1) ? v1 : v0);
            a[3] = __float_as_uint((lc & 1) ? v3 : v2);
#pragma unroll
            for (int nt = 0; nt < 8; nt++) {
                uint32_t bb[2];
                bb[0] = __float_as_uint(Vs[(ks * 8 + lc) * 72 + nt * 8 + lr]);
                bb[1] = __float_as_uint(Vs[(ks * 8 + 4 + lc) * 72 + nt * 8 + lr]);
                mma_tf32(oacc[nt], a, bb);
            }
        }
    }

    // Epilogue: AO written tf32-rounded for the O-projection GEMM
    float il0 = 1.f / llo, il1 = 1.f / lhi;
#pragma unroll
    for (int nt = 0; nt < 8; nt++) {
        int col = nt * 8 + 2 * lc;
        float* p0 = out + ((size_t)b * S_ + grow0) * E_ + h * D_ + col;
        float* p1 = out + ((size_t)b * S_ + grow1) * E_ + h * D_ + col;
        *(float2*)p0 = make_float2(to_tf32(oacc[nt][0] * il0),
                                   to_tf32(oacc[nt][1] * il0));
        *(float2*)p1 = make_float2(to_tf32(oacc[nt][2] * il1),
                                   to_tf32(oacc[nt][3] * il1));
    }
}

// ---------------------------------------------------------------------------
// Launch
// ---------------------------------------------------------------------------
extern "C" void kernel_launch(void* const* d_in, const int* in_sizes, int n_in,
                              void* d_out, int out_size) {
    const float* x     = (const float*)d_in[0];
    const int*   amask = (const int*)d_in[1];
    const float* wq    = (const float*)d_in[2];
    const float* wk    = (const float*)d_in[3];
    const float* wv    = (const float*)d_in[4];
    const float* wo    = (const float*)d_in[5];
    float* out = (float*)d_out;

    float *qp, *kp, *vp, *aop, *xt, *wqt, *wkt, *wvt, *wot;
    cudaGetSymbolAddress((void**)&qp, g_Q);
    cudaGetSymbolAddress((void**)&kp, g_K);
    cudaGetSymbolAddress((void**)&vp, g_V);
    cudaGetSymbolAddress((void**)&aop, g_AO);
    cudaGetSymbolAddress((void**)&xt, g_X);
    cudaGetSymbolAddress((void**)&wqt, g_WQ);
    cudaGetSymbolAddress((void**)&wkt, g_WK);
    cudaGetSymbolAddress((void**)&wvt, g_WV);
    cudaGetSymbolAddress((void**)&wot, g_WO);

    // One-time tf32 rounding of all GEMM inputs
    const int NCVT = (B_ * S_ * E_) / 4 + 4 * (E_ * E_) / 4;  // 3,145,728
    cvt_inputs<<<NCVT / 256, 256>>>(x, wq, wk, wv, wo, xt, wqt, wkt, wvt, wot);

    // Fused Q/K/V projections
    gemm_tf32<true><<<dim3(E_ / 128, (B_ * S_) / 128, 3), 256>>>(
        xt, wqt, wkt, wvt, qp, kp, vp);

    // Tensor-core flash attention
    size_t fa_smem = (128 * 68 + 64 * 68 + 64 * 72) * sizeof(float);
    cudaFuncSetAttribute(flash_tc, cudaFuncAttributeMaxDynamicSharedMemorySize,
                         (int)fa_smem);
    flash_tc<<<dim3(S_ / 128, B_ * H_), 256, fa_smem>>>(qp, kp, vp, amask, aop);

    // Output projection
    gemm_tf32<false><<<dim3(E_ / 128, (B_ * S_) / 128, 1), 256>>>(
        aop, wot, wot, wot, out, out, out);
}

// round 10
// speedup vs baseline: 1.3014x; 1.1689x over previous
#include <cuda_runtime.h>
#include <cuda_bf16.h>
#include <cstdint>

// Problem constants
#define B_ 4
#define S_ 2048
#define E_ 1024
#define H_ 16
#define D_ 64

// Scratch (device globals; no allocation allowed)
__device__ float g_Q[(size_t)B_ * H_ * S_ * D_];
__device__ float g_K[(size_t)B_ * H_ * S_ * D_];
__device__ float g_V[(size_t)B_ * H_ * S_ * D_];
__device__ float g_AO[(size_t)B_ * S_ * E_];
__device__ float g_X[(size_t)B_ * S_ * E_];    // tf32-rounded x
__device__ float g_WQ[(size_t)E_ * E_];        // tf32-rounded weights
__device__ float g_WK[(size_t)E_ * E_];
__device__ float g_WV[(size_t)E_ * E_];
__device__ float g_WO[(size_t)E_ * E_];

__device__ __forceinline__ float to_tf32(float x) {
    uint32_t u;
    asm("cvt.rna.tf32.f32 %0, %1;" : "=r"(u) : "f"(x));
    return __uint_as_float(u);
}

__device__ __forceinline__ float4 cvt4(float4 v) {
    return make_float4(to_tf32(v.x), to_tf32(v.y), to_tf32(v.z), to_tf32(v.w));
}

__device__ __forceinline__ void mma_tf32(float* c, const uint32_t* a, const uint32_t* b) {
    asm volatile(
        "mma.sync.aligned.m16n8k8.row.col.f32.tf32.tf32.f32 "
        "{%0,%1,%2,%3}, {%4,%5,%6,%7}, {%8,%9}, {%0,%1,%2,%3};"
        : "+f"(c[0]), "+f"(c[1]), "+f"(c[2]), "+f"(c[3])
        : "r"(a[0]), "r"(a[1]), "r"(a[2]), "r"(a[3]), "r"(b[0]), "r"(b[1]));
}

__device__ __forceinline__ void cp16(uint32_t dst, const void* src) {
    asm volatile("cp.async.cg.shared.global [%0], [%1], 16;"
                 :: "r"(dst), "l"(src) : "memory");
}
#define CP_COMMIT() asm volatile("cp.async.commit_group;" ::: "memory")
#define CP_WAIT1()  asm volatile("cp.async.wait_group 1;" ::: "memory")

// Smem tile [128 rows][32 floats]: col4-group XOR (row & 7). Conflict-free for
// both 16B cp.async stores and per-quad fragment LDS (8 rows x XOR-distinct
// groups cover all 32 banks exactly once).
__device__ __forceinline__ int SWZ32(int r, int c) {
    return r * 32 + ((((c) >> 2) ^ (r & 7)) << 2) + ((c) & 3);
}

// ---------------------------------------------------------------------------
// Input conversion: round x and the 4 weight matrices to tf32 once.
// ---------------------------------------------------------------------------
__global__ __launch_bounds__(256) void cvt_inputs(
    const float* __restrict__ x,
    const float* __restrict__ wq, const float* __restrict__ wk,
    const float* __restrict__ wv, const float* __restrict__ wo,
    float* __restrict__ xt,
    float* __restrict__ wqt, float* __restrict__ wkt,
    float* __restrict__ wvt, float* __restrict__ wot) {
    const int NX = (B_ * S_ * E_) / 4;   // 2,097,152
    const int NW = (E_ * E_) / 4;        // 262,144
    int i = blockIdx.x * 256 + threadIdx.x;
    if (i < NX) {
        ((float4*)xt)[i] = cvt4(((const float4*)x)[i]);
        return;
    }
    i -= NX;
    const float* s;
    float* d;
    if (i < NW)          { s = wq; d = wqt; }
    else if (i < 2 * NW) { s = wk; d = wkt; i -= NW; }
    else if (i < 3 * NW) { s = wv; d = wvt; i -= 2 * NW; }
    else                 { s = wo; d = wot; i -= 3 * NW; }
    ((float4*)d)[i] = cvt4(((const float4*)s)[i]);
}

// ---------------------------------------------------------------------------
// TF32 tensor-core GEMM: C[M,N] = A[M,K] * W[N,K]^T
// Inputs ALREADY tf32-rounded. K-chunk = 32 (one 128B atom row), 3-stage
// cp.async pipeline in dynamic smem (96 KB), ONE wait+sync per 64 MMAs.
// Tile 128x128, 256 threads, warp grid 2x4, warp tile 64x32.
// blockIdx.z selects (W, C). SPLIT=true writes [B,H,S,D] (tf32-rounded).
// ---------------------------------------------------------------------------
#define GEMM_SMEM (3 * 16384 * 2)   // 98304 B

template <bool SPLIT>
__global__ __launch_bounds__(256, 2) void gemm_tf32(
    const float* __restrict__ A,
    const float* __restrict__ W0, const float* __restrict__ W1,
    const float* __restrict__ W2,
    float* __restrict__ C0, float* __restrict__ C1, float* __restrict__ C2) {
    const int K = E_;
    extern __shared__ float dsm[];
    // As: dsm[0 .. 3*4096), Bs: dsm[12288 .. 12288+3*4096) (floats)

    const float* W = W0;
    float* C = C0;
    if (blockIdx.z == 1) { W = W1; C = C1; }
    else if (blockIdx.z == 2) { W = W2; C = C2; }

    const int tid = threadIdx.x;
    const int bm = blockIdx.y * 128, bn = blockIdx.x * 128;
    const int wid = tid >> 5, lane = tid & 31;
    const int lr = lane >> 2, lc = lane & 3;
    const int mb = (wid & 1) * 64;
    const int nb = (wid >> 1) * 32;

    // cp.async indexing: thread -> (r0 = tid>>3 in 0..31, cg = tid&7).
    // 4 passes cover 128 rows; each pass one 16B cp per operand.
    const int r0 = tid >> 3;
    const int cg = tid & 7;
    const uint32_t aoff = (uint32_t)(r0 * 128 + ((cg ^ (r0 & 7)) * 16));

    const uint32_t sa = (uint32_t)__cvta_generic_to_shared(dsm);
    const uint32_t sb = sa + 49152u;

    const float* Ap = A + (size_t)(bm + r0) * K + cg * 4;
    const float* Wp = W + (size_t)(bn + r0) * K + cg * 4;

    float acc[4][4][4];
#pragma unroll
    for (int mt = 0; mt < 4; mt++)
#pragma unroll
        for (int nt = 0; nt < 4; nt++)
#pragma unroll
            for (int i = 0; i < 4; i++) acc[mt][nt][i] = 0.f;

    const int NCHUNK = K / 32;  // 32

    // Prologue: issue chunks 0 and 1
#pragma unroll
    for (int c = 0; c < 2; c++) {
        const uint32_t st = (uint32_t)c * 16384u;
        const int kc = c * 32;
#pragma unroll
        for (int i = 0; i < 4; i++) {
            cp16(sa + st + aoff + i * 4096u, Ap + (size_t)(i * 32) * K + kc);
            cp16(sb + st + aoff + i * 4096u, Wp + (size_t)(i * 32) * K + kc);
        }
        CP_COMMIT();
    }

#pragma unroll 1
    for (int c = 0; c < NCHUNK; c++) {
        CP_WAIT1();
        __syncthreads();

        // Issue chunk c+2 into stage (c+2)%3 (consumed two iterations ago)
        if (c + 2 < NCHUNK) {
            const uint32_t st = (uint32_t)((c + 2) % 3) * 16384u;
            const int kc = (c + 2) * 32;
#pragma unroll
            for (int i = 0; i < 4; i++) {
                cp16(sa + st + aoff + i * 4096u, Ap + (size_t)(i * 32) * K + kc);
                cp16(sb + st + aoff + i * 4096u, Wp + (size_t)(i * 32) * K + kc);
            }
        }
        CP_COMMIT();

        // 64 MMAs on stage c%3 (4 k0-steps of 8)
        const float* Asb = dsm + (c % 3) * 4096;
        const float* Bsb = dsm + 12288 + (c % 3) * 4096;
#pragma unroll
        for (int k0 = 0; k0 < 32; k0 += 8) {
            uint32_t af[4][4], bf[4][2];
#pragma unroll
            for (int mt = 0; mt < 4; mt++) {
                int m = mb + mt * 16 + lr;
                af[mt][0] = __float_as_uint(Asb[SWZ32(m, k0 + lc)]);
                af[mt][1] = __float_as_uint(Asb[SWZ32(m + 8, k0 + lc)]);
                af[mt][2] = __float_as_uint(Asb[SWZ32(m, k0 + 4 + lc)]);
                af[mt][3] = __float_as_uint(Asb[SWZ32(m + 8, k0 + 4 + lc)]);
            }
#pragma unroll
            for (int nt = 0; nt < 4; nt++) {
                int n = nb + nt * 8 + lr;
                bf[nt][0] = __float_as_uint(Bsb[SWZ32(n, k0 + lc)]);
                bf[nt][1] = __float_as_uint(Bsb[SWZ32(n, k0 + 4 + lc)]);
            }
#pragma unroll
            for (int mt = 0; mt < 4; mt++)
#pragma unroll
                for (int nt = 0; nt < 4; nt++)
                    mma_tf32(acc[mt][nt], af[mt], bf[nt]);
        }
    }

    // Epilogue (SPLIT path pre-rounds to tf32 for the flash consumer)
#pragma unroll
    for (int mt = 0; mt < 4; mt++) {
#pragma unroll
        for (int nt = 0; nt < 4; nt++) {
            int row = bm + mb + mt * 16 + lr;
            int col = bn + nb + nt * 8 + lc * 2;
#pragma unroll
            for (int half = 0; half < 2; half++) {
                int m = row + half * 8;
                float v0 = acc[mt][nt][half * 2], v1 = acc[mt][nt][half * 2 + 1];
                if (!SPLIT) {
                    *(float2*)(C + (size_t)m * E_ + col) = make_float2(v0, v1);
                } else {
                    int b = m >> 11, sq = m & 2047;
                    int h = col >> 6, d = col & 63;
                    *(float2*)(C + ((((size_t)b * H_ + h) * S_ + sq) * D_ + d)) =
                        make_float2(to_tf32(v0), to_tf32(v1));
                }
            }
        }
    }
}

// ---------------------------------------------------------------------------
// Tensor-core flash attention (tf32 mma, fp32 softmax). Unchanged from R9.
// Q/K/V already tf32-rounded; AO written tf32-rounded.
// ---------------------------------------------------------------------------
__global__ __launch_bounds__(256) void flash_tc(const float* __restrict__ Q,
                                                const float* __restrict__ K,
                                                const float* __restrict__ V,
                                                const int* __restrict__ amask,
                                                float* __restrict__ out) {
    extern __shared__ float smf[];
    float* Qs = smf;                   // 128 x 68
    float* Ks = Qs + 128 * 68;         // 64 x 68
    float* Vs = Ks + 64 * 68;          // 64 x 72
    __shared__ unsigned mkb[2];

    const int tid = threadIdx.x;
    const int qt = blockIdx.x;
    const int bh = blockIdx.y;
    const int b = bh >> 4, h = bh & 15;
    const int qbase = qt * 128;

    const int lane = tid & 31, wid = tid >> 5;
    const int lr = lane >> 2, lc = lane & 3;
    const int wb = wid * 16;

    {
        const float* Qb = Q + ((size_t)bh * S_ + qbase) * D_;
        for (int e = tid; e < 2048; e += 256) {
            int r = e >> 4, c4 = e & 15;
            float4 v = ((const float4*)Qb)[e];
            *(float4*)&Qs[r * 68 + c4 * 4] =
                make_float4(v.x * 0.125f, v.y * 0.125f, v.z * 0.125f, v.w * 0.125f);
        }
    }

    const int grow0 = qbase + wb + lr;
    const int grow1 = grow0 + 8;

    float oacc[8][4];
#pragma unroll
    for (int nt = 0; nt < 8; nt++)
#pragma unroll
        for (int j = 0; j < 4; j++) oacc[nt][j] = 0.f;

    float mlo = -1e30f, mhi = -1e30f, llo = 0.f, lhi = 0.f;

    const int ntiles = 2 * qt + 2;
    for (int kt = 0; kt < ntiles; kt++) {
        __syncthreads();

        const float* Kb = K + ((size_t)bh * S_ + kt * 64) * D_;
        const float* Vb = V + ((size_t)bh * S_ + kt * 64) * D_;
        for (int e = tid; e < 1024; e += 256) {
            int r = e >> 4, c4 = e & 15;
            *(float4*)&Ks[r * 68 + c4 * 4] = ((const float4*)Kb)[e];
            *(float4*)&Vs[r * 72 + c4 * 4] = ((const float4*)Vb)[e];
        }
        if (tid < 64) {
            int m = amask[b * S_ + kt * 64 + tid];
            unsigned bal = __ballot_sync(0xffffffffu, m != 0);
            if ((tid & 31) == 0) mkb[tid >> 5] = bal;
        }
        __syncthreads();

        float sacc[8][4];
#pragma unroll
        for (int nt = 0; nt < 8; nt++)
#pragma unroll
            for (int j = 0; j < 4; j++) sacc[nt][j] = 0.f;

#pragma unroll
        for (int ks = 0; ks < 8; ks++) {
            int k0 = ks * 8;
            uint32_t a[4];
            a[0] = __float_as_uint(Qs[(wb + lr) * 68 + k0 + lc]);
            a[1] = __float_as_uint(Qs[(wb + lr + 8) * 68 + k0 + lc]);
            a[2] = __float_as_uint(Qs[(wb + lr) * 68 + k0 + 4 + lc]);
            a[3] = __float_as_uint(Qs[(wb + lr + 8) * 68 + k0 + 4 + lc]);
#pragma unroll
            for (int nt = 0; nt < 8; nt++) {
                uint32_t bb[2];
                bb[0] = __float_as_uint(Ks[(nt * 8 + lr) * 68 + k0 + lc]);
                bb[1] = __float_as_uint(Ks[(nt * 8 + lr) * 68 + k0 + 4 + lc]);
                mma_tf32(sacc[nt], a, bb);
            }
        }

        unsigned mb0 = mkb[0], mb1 = mkb[1];
        bool diag = (kt >= 2 * qt);
        bool pad = (mb0 & mb1) != 0xffffffffu;
        if (diag || pad) {
#pragma unroll
            for (int nt = 0; nt < 8; nt++) {
#pragma unroll
                for (int j = 0; j < 4; j++) {
                    int colL = nt * 8 + 2 * lc + (j & 1);
                    int gcol = kt * 64 + colL;
                    int grow = (j < 2) ? grow0 : grow1;
                    unsigned bit = ((colL < 32 ? mb0 : mb1) >> (colL & 31)) & 1u;
                    if (!bit || gcol > grow) sacc[nt][j] = -1e30f;
                }
            }
        }

        float tlo = -1e30f, thi = -1e30f;
#pragma unroll
        for (int nt = 0; nt < 8; nt++) {
            tlo = fmaxf(tlo, fmaxf(sacc[nt][0], sacc[nt][1]));
            thi = fmaxf(thi, fmaxf(sacc[nt][2], sacc[nt][3]));
        }
        tlo = fmaxf(tlo, __shfl_xor_sync(0xffffffffu, tlo, 1));
        tlo = fmaxf(tlo, __shfl_xor_sync(0xffffffffu, tlo, 2));
        thi = fmaxf(thi, __shfl_xor_sync(0xffffffffu, thi, 1));
        thi = fmaxf(thi, __shfl_xor_sync(0xffffffffu, thi, 2));

        float nmlo = fmaxf(mlo, tlo), nmhi = fmaxf(mhi, thi);
        float alo = __expf(mlo - nmlo), ahi = __expf(mhi - nmhi);
        mlo = nmlo; mhi = nmhi;

        float slo = 0.f, shi = 0.f;
#pragma unroll
        for (int nt = 0; nt < 8; nt++) {
            float p0 = to_tf32(__expf(sacc[nt][0] - nmlo));
            float p1 = to_tf32(__expf(sacc[nt][1] - nmlo));
            float p2 = to_tf32(__expf(sacc[nt][2] - nmhi));
            float p3 = to_tf32(__expf(sacc[nt][3] - nmhi));
            sacc[nt][0] = p0; sacc[nt][1] = p1;
            sacc[nt][2] = p2; sacc[nt][3] = p3;
            slo += p0 + p1; shi += p2 + p3;
        }
        slo += __shfl_xor_sync(0xffffffffu, slo, 1);
        slo += __shfl_xor_sync(0xffffffffu, slo, 2);
        shi += __shfl_xor_sync(0xffffffffu, shi, 1);
        shi += __shfl_xor_sync(0xffffffffu, shi, 2);
        llo = llo * alo + slo;
        lhi = lhi * ahi + shi;

#pragma unroll
        for (int nt = 0; nt < 8; nt++) {
            oacc[nt][0] *= alo; oacc[nt][1] *= alo;
            oacc[nt][2] *= ahi; oacc[nt][3] *= ahi;
        }

        const int src0 = (lane & 28) | (lc >> 1);
        const int src1 = src0 + 2;
#pragma unroll
        for (int ks = 0; ks < 8; ks++) {
            float p0 = sacc[ks][0], p1 = sacc[ks][1];
            float p2 = sacc[ks][2], p3 = sacc[ks][3];
            float u0 = __shfl_sync(0xffffffffu, p0, src0);
            float u1 = __shfl_sync(0xffffffffu, p1, src0);
            float u2 = __shfl_sync(0xffffffffu, p2, src0);
            float u3 = __shfl_sync(0xffffffffu, p3, src0);
            float v0 = __shfl_sync(0xffffffffu, p0, src1);
            float v1 = __shfl_sync(0xffffffffu, p1, src1);
            float v2 = __shfl_sync(0xffffffffu, p2, src1);
            float v3 = __shfl_sync(0xffffffffu, p3, src1);
            uint32_t a[4];
            a[0] = __float_as_uint((lc & 1) ? u1 : u0);
            a[1] = __float_as_uint((lc & 1) ? u3 : u2);
            a[2] = __float_as_uint((lc & 1) ? v1 : v0);
            a[3] = __float_as_uint((lc & 1) ? v3 : v2);
#pragma unroll
            for (int nt = 0; nt < 8; nt++) {
                uint32_t bb[2];
                bb[0] = __float_as_uint(Vs[(ks * 8 + lc) * 72 + nt * 8 + lr]);
                bb[1] = __float_as_uint(Vs[(ks * 8 + 4 + lc) * 72 + nt * 8 + lr]);
                mma_tf32(oacc[nt], a, bb);
            }
        }
    }

    float il0 = 1.f / llo, il1 = 1.f / lhi;
#pragma unroll
    for (int nt = 0; nt < 8; nt++) {
        int col = nt * 8 + 2 * lc;
        float* p0 = out + ((size_t)b * S_ + grow0) * E_ + h * D_ + col;
        float* p1 = out + ((size_t)b * S_ + grow1) * E_ + h * D_ + col;
        *(float2*)p0 = make_float2(to_tf32(oacc[nt][0] * il0),
                                   to_tf32(oacc[nt][1] * il0));
        *(float2*)p1 = make_float2(to_tf32(oacc[nt][2] * il1),
                                   to_tf32(oacc[nt][3] * il1));
    }
}

// ---------------------------------------------------------------------------
// Launch
// ---------------------------------------------------------------------------
extern "C" void kernel_launch(void* const* d_in, const int* in_sizes, int n_in,
                              void* d_out, int out_size) {
    const float* x     = (const float*)d_in[0];
    const int*   amask = (const int*)d_in[1];
    const float* wq    = (const float*)d_in[2];
    const float* wk    = (const float*)d_in[3];
    const float* wv    = (const float*)d_in[4];
    const float* wo    = (const float*)d_in[5];
    float* out = (float*)d_out;

    float *qp, *kp, *vp, *aop, *xt, *wqt, *wkt, *wvt, *wot;
    cudaGetSymbolAddress((void**)&qp, g_Q);
    cudaGetSymbolAddress((void**)&kp, g_K);
    cudaGetSymbolAddress((void**)&vp, g_V);
    cudaGetSymbolAddress((void**)&aop, g_AO);
    cudaGetSymbolAddress((void**)&xt, g_X);
    cudaGetSymbolAddress((void**)&wqt, g_WQ);
    cudaGetSymbolAddress((void**)&wkt, g_WK);
    cudaGetSymbolAddress((void**)&wvt, g_WV);
    cudaGetSymbolAddress((void**)&wot, g_WO);

    // One-time tf32 rounding of all GEMM inputs
    const int NCVT = (B_ * S_ * E_) / 4 + 4 * (E_ * E_) / 4;  // 3,145,728
    cvt_inputs<<<NCVT / 256, 256>>>(x, wq, wk, wv, wo, xt, wqt, wkt, wvt, wot);

    cudaFuncSetAttribute(gemm_tf32<true>,
                         cudaFuncAttributeMaxDynamicSharedMemorySize, GEMM_SMEM);
    cudaFuncSetAttribute(gemm_tf32<false>,
                         cudaFuncAttributeMaxDynamicSharedMemorySize, GEMM_SMEM);

    // Fused Q/K/V projections
    gemm_tf32<true><<<dim3(E_ / 128, (B_ * S_) / 128, 3), 256, GEMM_SMEM>>>(
        xt, wqt, wkt, wvt, qp, kp, vp);

    // Tensor-core flash attention
    size_t fa_smem = (128 * 68 + 64 * 68 + 64 * 72) * sizeof(float);
    cudaFuncSetAttribute(flash_tc, cudaFuncAttributeMaxDynamicSharedMemorySize,
                         (int)fa_smem);
    flash_tc<<<dim3(S_ / 128, B_ * H_), 256, fa_smem>>>(qp, kp, vp, amask, aop);

    // Output projection
    gemm_tf32<false><<<dim3(E_ / 128, (B_ * S_) / 128, 1), 256, GEMM_SMEM>>>(
        aop, wot, wot, wot, out, out, out);
}